// round 1
// baseline (speedup 1.0000x reference)
#include <cuda_runtime.h>
#include <math.h>

// ---------------- scratch (no allocation allowed) ----------------
#define MAXB 16
#define MAXN 256
#define MAXBLOCKS 8192

__device__ float g_ccy[MAXB * MAXN];
__device__ float g_ccx[MAXB * MAXN];
__device__ float g_cinv[MAXB * MAXN];
__device__ float g_partial[MAXBLOCKS * 2];

// ---------------- tile config ----------------
#define TILE 32
#define TDX 32
#define TDY 8
#define RPT 4   // rows per thread (TDY*RPT = TILE)
#define CULL_T 110.0f   // expf(-x)==0 exactly for x>103.98; margin

// Precompute per-center (cy, cx, 1/(2*sigma^2)).
// sigma = PR_MIN/gr + relu(sm[cy,cx]) * REF_GROUND_RES / gr, both consts 0.2,
// computed with the same association as the JAX reference.
__global__ void prep_kernel(const float* __restrict__ sm,
                            const float* __restrict__ gr,
                            const int* __restrict__ centers,
                            int H, int W, int N) {
    int b = blockIdx.x;
    int n = threadIdx.x;
    if (n >= N) return;
    int cy = centers[(b * N + n) * 2 + 0];
    int cx = centers[(b * N + n) * 2 + 1];
    // reference: jnp.clip(c, 0, H-1) on both coords
    cy = min(max(cy, 0), H - 1);
    cx = min(max(cx, 0), H - 1);
    float smv = sm[(size_t)b * H * W + (size_t)cy * W + cx];
    float g = gr[b];
    float t = 0.2f / g;                       // PR_MIN / gr
    float relu = fmaxf(smv, 0.0f);
    float size = t + (relu * 0.2f) / g;       // + relu*RES/gr (same assoc as ref)
    float inv = 1.0f / (2.0f * size * size);
    g_ccy[b * MAXN + n] = (float)cy;
    g_ccx[b * MAXN + n] = (float)cx;
    g_cinv[b * MAXN + n] = inv;
}

// Main fused kernel: per 32x32 tile — cull centers, max-splat gaussians,
// write gts, accumulate per-block partial sums of (hm-gt)^2*mask and sm^2.
__global__ __launch_bounds__(TDX * TDY)
void splat_kernel(const float* __restrict__ hm,
                  const float* __restrict__ sm,
                  const float* __restrict__ mask,
                  float* __restrict__ gts,
                  int H, int W, int N) {
    int b = blockIdx.z;
    int x0 = blockIdx.x * TILE;
    int y0 = blockIdx.y * TILE;
    int tid = threadIdx.y * TDX + threadIdx.x;

    __shared__ float scy[MAXN], scx[MAXN], sinv[MAXN];
    __shared__ int s_ns;
    if (tid == 0) s_ns = 0;
    __syncthreads();

    // ---- exact cull: closest point of tile rect to center ----
    float fx0 = (float)x0, fx1 = (float)(x0 + TILE - 1);
    float fy0 = (float)y0, fy1 = (float)(y0 + TILE - 1);
    for (int i = tid; i < N; i += TDX * TDY) {
        float cy = g_ccy[b * MAXN + i];
        float cx = g_ccx[b * MAXN + i];
        float inv = g_cinv[b * MAXN + i];
        float ddx = fmaxf(fmaxf(fx0 - cx, cx - fx1), 0.0f);
        float ddy = fmaxf(fmaxf(fy0 - cy, cy - fy1), 0.0f);
        float d2min = ddx * ddx + ddy * ddy;
        if (d2min * inv <= CULL_T) {
            int k = atomicAdd(&s_ns, 1);   // order-free: min below is commutative
            scy[k] = cy; scx[k] = cx; sinv[k] = inv;
        }
    }
    __syncthreads();
    int ns = s_ns;

    // ---- per-thread: one column x, RPT rows strided by TDY ----
    int x = x0 + threadIdx.x;
    float xf = (float)x;
    float ybase = (float)(y0 + threadIdx.y);

    float m0 = 1e30f, m1 = 1e30f, m2 = 1e30f, m3 = 1e30f;
    for (int i = 0; i < ns; i++) {
        float cx = scx[i], cy = scy[i], inv = sinv[i];
        float dx = xf - cx;
        float bx = dx * dx * inv;
        float dy = ybase - cy;
        float d;
        d = dy;                 m0 = fminf(m0, fmaf(d * d, inv, bx));
        d = dy + (float)TDY;    m1 = fminf(m1, fmaf(d * d, inv, bx));
        d = dy + (float)(2*TDY);m2 = fminf(m2, fmaf(d * d, inv, bx));
        d = dy + (float)(3*TDY);m3 = fminf(m3, fmaf(d * d, inv, bx));
    }

    // ---- epilogue: gt = exp(-m), write out, accumulate losses ----
    size_t base = (size_t)b * H * W;
    float ms[RPT] = {m0, m1, m2, m3};
    float lsum_hm = 0.0f, lsum_sm = 0.0f;
#pragma unroll
    for (int r = 0; r < RPT; r++) {
        int y = y0 + threadIdx.y + r * TDY;
        size_t idx = base + (size_t)y * W + x;
        float gt = expf(-ms[r]);               // expf(-1e30) == 0 when no survivors
        float h = hm[idx];
        float mk = mask[idx];
        float s = sm[idx];
        gts[idx] = gt;
        float dd = h - gt;
        lsum_hm = fmaf(dd * dd, mk, lsum_hm);
        lsum_sm = fmaf(s, s, lsum_sm);
    }

    // ---- deterministic block reduction ----
    __shared__ float rh[TDX * TDY];
    __shared__ float rs[TDX * TDY];
    rh[tid] = lsum_hm;
    rs[tid] = lsum_sm;
    __syncthreads();
    for (int sft = (TDX * TDY) / 2; sft > 0; sft >>= 1) {
        if (tid < sft) { rh[tid] += rh[tid + sft]; rs[tid] += rs[tid + sft]; }
        __syncthreads();
    }
    if (tid == 0) {
        int blin = (b * gridDim.y + blockIdx.y) * gridDim.x + blockIdx.x;
        g_partial[2 * blin + 0] = rh[0];
        g_partial[2 * blin + 1] = rs[0];
    }
}

// Fixed-order final reduction of per-block partials -> out[0], out[1].
__global__ void finish_kernel(float* __restrict__ out, int nblocks, float invCount) {
    __shared__ float rh[256], rs[256];
    int tid = threadIdx.x;
    float sh = 0.0f, ss = 0.0f;
    for (int i = tid; i < nblocks; i += 256) {
        sh += g_partial[2 * i + 0];
        ss += g_partial[2 * i + 1];
    }
    rh[tid] = sh; rs[tid] = ss;
    __syncthreads();
    for (int sft = 128; sft > 0; sft >>= 1) {
        if (tid < sft) { rh[tid] += rh[tid + sft]; rs[tid] += rs[tid + sft]; }
        __syncthreads();
    }
    if (tid == 0) {
        out[0] = rs[0] * invCount;   // scale_loss = mean(sm^2)
        out[1] = rh[0] * invCount;   // hm_loss    = mean((hm-gt)^2 * mask)
    }
}

extern "C" void kernel_launch(void* const* d_in, const int* in_sizes, int n_in,
                              void* d_out, int out_size) {
    const float* hm      = (const float*)d_in[0];
    const float* sm      = (const float*)d_in[1];
    const float* gr      = (const float*)d_in[2];
    const float* mask    = (const float*)d_in[3];
    const int*   centers = (const int*)  d_in[4];

    int B  = in_sizes[2];                 // ground_resolution: [B]
    int HW = in_sizes[0] / B;             // pred_hm: [B,1,H,W]
    int H  = 1;
    while ((long long)H * H < (long long)HW) H++;   // 512
    int W  = HW / H;
    int N  = in_sizes[4] / (2 * B);       // centers: [B,N,2]

    float* out = (float*)d_out;
    // flattened tuple: [scale_loss, hm_loss, gts...]
    float* gts = out + (out_size - (size_t)B * HW);

    prep_kernel<<<B, N>>>(sm, gr, centers, H, W, N);

    dim3 grid(W / TILE, H / TILE, B);
    dim3 block(TDX, TDY);
    splat_kernel<<<grid, block>>>(hm, sm, mask, gts, H, W, N);

    int nblocks = B * (H / TILE) * (W / TILE);
    finish_kernel<<<1, 256>>>(out, nblocks, 1.0f / ((float)B * (float)HW));
}

// round 3
// speedup vs baseline: 1.2113x; 1.2113x over previous
#include <cuda_runtime.h>
#include <math.h>

// ---------------- scratch (no allocation allowed) ----------------
#define MAXN 256
#define MAXBLOCKS 8192

__device__ float g_partial[MAXBLOCKS * 2];
__device__ unsigned int g_count = 0;

// ---------------- tile config ----------------
#define TX 128          // tile width  (32 threads x 4 cols)
#define TY 16           // tile height (8 thread-rows x 2 rows/thread)
#define BDX 32
#define BDY 8
#define NTHR (BDX * BDY)
#define CULL_T 110.0f   // expf(-x) == 0 exactly for x > 103.98; margin

// Single fused kernel:
//  phase A: per-block recompute of center params (sigma -> inv2sig2) + exact tile cull
//  phase B: max-splat gaussian arguments, expf epilogue, gts write, loss partials
//  phase C: last-block-done deterministic final reduction -> out[0], out[1]
__global__ __launch_bounds__(NTHR)
void fused_kernel(const float* __restrict__ hm,
                  const float* __restrict__ sm,
                  const float* __restrict__ mask,
                  const float* __restrict__ gr,
                  const int*   __restrict__ centers,
                  float* __restrict__ gts,    // NOTE: only 8-byte aligned (d_out + 2)
                  float* __restrict__ out,
                  int H, int W, int N, int nblocks, float invCount) {
    int b  = blockIdx.z;
    int x0 = blockIdx.x * TX;
    int y0 = blockIdx.y * TY;
    int tid = threadIdx.y * BDX + threadIdx.x;

    __shared__ float scy[MAXN], scx[MAXN], sinv[MAXN];
    __shared__ int s_ns;
    if (tid == 0) s_ns = 0;
    __syncthreads();

    // ---- phase A: param compute + exact cull (closest point of tile rect) ----
    {
        float g = __ldg(&gr[b]);
        float t = 0.2f / g;                         // PR_MIN / gr
        float fx0 = (float)x0;
        float fx1 = (float)min(x0 + TX - 1, W - 1);
        float fy0 = (float)y0;
        float fy1 = (float)min(y0 + TY - 1, H - 1);
        const int2* cptr = (const int2*)centers;
        size_t sbase = (size_t)b * H * W;
        for (int i = tid; i < N; i += NTHR) {
            int2 c = __ldg(&cptr[b * N + i]);
            int cy = min(max(c.x, 0), H - 1);       // reference clamps both to H-1
            int cx = min(max(c.y, 0), H - 1);
            float smv = __ldg(&sm[sbase + (size_t)cy * W + cx]);
            float relu = fmaxf(smv, 0.0f);
            float size = t + (relu * 0.2f) / g;     // same association as reference
            float inv = 1.0f / (2.0f * size * size);
            float fcx = (float)cx, fcy = (float)cy;
            float ddx = fmaxf(fmaxf(fx0 - fcx, fcx - fx1), 0.0f);
            float ddy = fmaxf(fmaxf(fy0 - fcy, fcy - fy1), 0.0f);
            float d2min = ddx * ddx + ddy * ddy;
            if (d2min * inv <= CULL_T) {
                int k = atomicAdd(&s_ns, 1);        // order-free: fmin is commutative/exact
                scy[k] = fcy; scx[k] = fcx; sinv[k] = inv;
            }
        }
    }
    __syncthreads();
    int ns = s_ns;

    // ---- phase B: each thread = 4 consecutive cols x 2 rows ----
    int x4 = x0 + threadIdx.x * 4;
    int y  = y0 + threadIdx.y;          // rows y and y + BDY
    float fx = (float)x4;
    float fy = (float)y;

    float m00 = 1e30f, m01 = 1e30f, m02 = 1e30f, m03 = 1e30f;
    float m10 = 1e30f, m11 = 1e30f, m12 = 1e30f, m13 = 1e30f;

    for (int i = 0; i < ns; i++) {
        float cx = scx[i], cy = scy[i], inv = sinv[i];
        float dx0 = fx - cx;
        float dx1 = dx0 + 1.0f, dx2 = dx0 + 2.0f, dx3 = dx0 + 3.0f;
        float b0 = dx0 * dx0 * inv;
        float b1 = dx1 * dx1 * inv;
        float b2 = dx2 * dx2 * inv;
        float b3 = dx3 * dx3 * inv;
        float dy0 = fy - cy;
        float dy1 = dy0 + (float)BDY;
        float a0 = dy0 * dy0 * inv;
        float a1 = dy1 * dy1 * inv;
        m00 = fminf(m00, a0 + b0); m01 = fminf(m01, a0 + b1);
        m02 = fminf(m02, a0 + b2); m03 = fminf(m03, a0 + b3);
        m10 = fminf(m10, a1 + b0); m11 = fminf(m11, a1 + b1);
        m12 = fminf(m12, a1 + b2); m13 = fminf(m13, a1 + b3);
    }

    // ---- epilogue: gt = exp(-m), float4 input loads, float2 gts stores ----
    float lsum_hm = 0.0f, lsum_sm = 0.0f;
    size_t base = (size_t)b * H * W;
    bool xok = (x4 + 3) < W;

    float mrow[2][4] = {{m00, m01, m02, m03}, {m10, m11, m12, m13}};
#pragma unroll
    for (int r = 0; r < 2; r++) {
        int yy = y + r * BDY;
        if (xok && yy < H) {
            size_t idx = base + (size_t)yy * W + x4;
            float4 h4 = *(const float4*)(hm + idx);
            float4 k4 = *(const float4*)(mask + idx);
            float4 s4 = *(const float4*)(sm + idx);
            float4 g4;
            g4.x = expf(-mrow[r][0]);
            g4.y = expf(-mrow[r][1]);
            g4.z = expf(-mrow[r][2]);
            g4.w = expf(-mrow[r][3]);
            // gts is d_out+2 floats: 8B-aligned only -> use two float2 stores
            *(float2*)(gts + idx)     = make_float2(g4.x, g4.y);
            *(float2*)(gts + idx + 2) = make_float2(g4.z, g4.w);
            float d;
            d = h4.x - g4.x; lsum_hm = fmaf(d * d, k4.x, lsum_hm);
            d = h4.y - g4.y; lsum_hm = fmaf(d * d, k4.y, lsum_hm);
            d = h4.z - g4.z; lsum_hm = fmaf(d * d, k4.z, lsum_hm);
            d = h4.w - g4.w; lsum_hm = fmaf(d * d, k4.w, lsum_hm);
            lsum_sm = fmaf(s4.x, s4.x, lsum_sm);
            lsum_sm = fmaf(s4.y, s4.y, lsum_sm);
            lsum_sm = fmaf(s4.z, s4.z, lsum_sm);
            lsum_sm = fmaf(s4.w, s4.w, lsum_sm);
        }
    }

    // ---- deterministic block reduction ----
    __shared__ float rh[NTHR];
    __shared__ float rs[NTHR];
    rh[tid] = lsum_hm;
    rs[tid] = lsum_sm;
    __syncthreads();
    for (int sft = NTHR / 2; sft > 0; sft >>= 1) {
        if (tid < sft) { rh[tid] += rh[tid + sft]; rs[tid] += rs[tid + sft]; }
        __syncthreads();
    }

    __shared__ int isLast;
    if (tid == 0) {
        int blin = (b * gridDim.y + blockIdx.y) * gridDim.x + blockIdx.x;
        g_partial[2 * blin + 0] = rh[0];
        g_partial[2 * blin + 1] = rs[0];
        __threadfence();
        unsigned int v = atomicAdd(&g_count, 1u);
        isLast = (v == (unsigned int)(nblocks - 1));
    }
    __syncthreads();

    // ---- phase C: last block does fixed-order final reduction ----
    if (isLast) {
        volatile float* vp = g_partial;
        float sh = 0.0f, ss = 0.0f;
        for (int i = tid; i < nblocks; i += NTHR) {
            sh += vp[2 * i + 0];
            ss += vp[2 * i + 1];
        }
        rh[tid] = sh; rs[tid] = ss;
        __syncthreads();
        for (int sft = NTHR / 2; sft > 0; sft >>= 1) {
            if (tid < sft) { rh[tid] += rh[tid + sft]; rs[tid] += rs[tid + sft]; }
            __syncthreads();
        }
        if (tid == 0) {
            out[0] = rs[0] * invCount;   // scale_loss = mean(sm^2)
            out[1] = rh[0] * invCount;   // hm_loss    = mean((hm-gt)^2 * mask)
            g_count = 0;                 // reset for next graph replay
        }
    }
}

extern "C" void kernel_launch(void* const* d_in, const int* in_sizes, int n_in,
                              void* d_out, int out_size) {
    const float* hm      = (const float*)d_in[0];
    const float* sm      = (const float*)d_in[1];
    const float* gr      = (const float*)d_in[2];
    const float* mask    = (const float*)d_in[3];
    const int*   centers = (const int*)  d_in[4];

    int B  = in_sizes[2];                 // ground_resolution: [B]
    int HW = in_sizes[0] / B;             // pred_hm: [B,1,H,W]
    int H  = 1;
    while ((long long)H * H < (long long)HW) H++;   // 512
    int W  = HW / H;
    int N  = in_sizes[4] / (2 * B);       // centers: [B,N,2]

    float* out = (float*)d_out;
    float* gts = out + (out_size - (size_t)B * HW); // tuple: [sl, hl, gts...]

    dim3 grid((W + TX - 1) / TX, (H + TY - 1) / TY, B);
    dim3 block(BDX, BDY);
    int nblocks = grid.x * grid.y * grid.z;
    fused_kernel<<<grid, block>>>(hm, sm, mask, gr, centers, gts, out,
                                  H, W, N, nblocks,
                                  1.0f / ((float)B * (float)HW));
}

// round 4
// speedup vs baseline: 1.8200x; 1.5025x over previous
#include <cuda_runtime.h>
#include <math.h>

// ---------------- scratch (no allocation allowed) ----------------
#define MAXN 256
#define MAXBLOCKS 8192

__device__ float g_partial[MAXBLOCKS * 2];
__device__ unsigned int g_count = 0;

// ---------------- tile config ----------------
#define TX 128          // tile width  (32 threads x 4 cols)
#define TY 16           // tile height (8 thread-rows x 2 rows/thread)
#define BDX 32
#define BDY 8
#define NTHR (BDX * BDY)
#define CULL_T 110.0f   // exp(-x) underflows to 0 in f32 for x > ~104; margin
#define LOG2E 1.4426950408889634f

__device__ __forceinline__ float ex2_approx(float x) {
    float r;
    asm("ex2.approx.ftz.f32 %0, %1;" : "=f"(r) : "f"(x));
    return r;
}

// Single fused kernel:
//  phase A: per-block center param recompute (inv2sig2 * log2e) + exact tile cull
//  phase B: min-splat of gaussian log2-arguments, single EX2 epilogue, gts write
//  phase C: last-block-done deterministic final reduction -> out[0], out[1]
__global__ __launch_bounds__(NTHR)
void fused_kernel(const float* __restrict__ hm,
                  const float* __restrict__ sm,
                  const float* __restrict__ mask,
                  const float* __restrict__ gr,
                  const int*   __restrict__ centers,
                  float* __restrict__ gts,    // NOTE: only 8-byte aligned (d_out + 2)
                  float* __restrict__ out,
                  int H, int W, int N, int nblocks, float invCount) {
    int b  = blockIdx.z;
    int x0 = blockIdx.x * TX;
    int y0 = blockIdx.y * TY;
    int tid = threadIdx.y * BDX + threadIdx.x;

    __shared__ float scy[MAXN], scx[MAXN], sinv[MAXN];
    __shared__ int s_ns;
    if (tid == 0) s_ns = 0;
    __syncthreads();

    // ---- phase A: param compute + exact cull (closest point of tile rect) ----
    {
        float g = __ldg(&gr[b]);
        float t = 0.2f / g;                         // PR_MIN / gr
        float fx0 = (float)x0;
        float fx1 = (float)min(x0 + TX - 1, W - 1);
        float fy0 = (float)y0;
        float fy1 = (float)min(y0 + TY - 1, H - 1);
        const int2* cptr = (const int2*)centers;
        int sbase = b * H * W;
        for (int i = tid; i < N; i += NTHR) {
            int2 c = __ldg(&cptr[b * N + i]);
            int cy = min(max(c.x, 0), H - 1);       // reference clamps both to H-1
            int cx = min(max(c.y, 0), H - 1);
            float smv = __ldg(&sm[sbase + cy * W + cx]);
            float relu = fmaxf(smv, 0.0f);
            float size = t + (relu * 0.2f) / g;     // same association as reference
            float inv = 1.0f / (2.0f * size * size);
            float fcx = (float)cx, fcy = (float)cy;
            float ddx = fmaxf(fmaxf(fx0 - fcx, fcx - fx1), 0.0f);
            float ddy = fmaxf(fmaxf(fy0 - fcy, fcy - fy1), 0.0f);
            float d2min = ddx * ddx + ddy * ddy;
            if (d2min * inv <= CULL_T) {            // cull in natural-log units
                int k = atomicAdd(&s_ns, 1);        // order-free: fmin is commutative/exact
                scy[k] = fcy; scx[k] = fcx;
                sinv[k] = inv * LOG2E;              // store in log2 units -> single EX2 later
            }
        }
    }
    __syncthreads();
    int ns = s_ns;

    // ---- phase B: each thread = 4 consecutive cols x 2 rows ----
    int x4 = x0 + threadIdx.x * 4;
    int y  = y0 + threadIdx.y;          // rows y and y + BDY
    float fx = (float)x4;
    float fy = (float)y;

    float m00 = 1e30f, m01 = 1e30f, m02 = 1e30f, m03 = 1e30f;
    float m10 = 1e30f, m11 = 1e30f, m12 = 1e30f, m13 = 1e30f;

    for (int i = 0; i < ns; i++) {
        float cx = scx[i], cy = scy[i], inv = sinv[i];
        float dx0 = fx - cx;
        float dx1 = dx0 + 1.0f, dx2 = dx0 + 2.0f, dx3 = dx0 + 3.0f;
        float b0 = dx0 * dx0 * inv;
        float b1 = dx1 * dx1 * inv;
        float b2 = dx2 * dx2 * inv;
        float b3 = dx3 * dx3 * inv;
        float dy0 = fy - cy;
        float dy1 = dy0 + (float)BDY;
        float a0 = dy0 * dy0 * inv;
        float a1 = dy1 * dy1 * inv;
        m00 = fminf(m00, a0 + b0); m01 = fminf(m01, a0 + b1);
        m02 = fminf(m02, a0 + b2); m03 = fminf(m03, a0 + b3);
        m10 = fminf(m10, a1 + b0); m11 = fminf(m11, a1 + b1);
        m12 = fminf(m12, a1 + b2); m13 = fminf(m13, a1 + b3);
    }

    // ---- epilogue: gt = 2^(-m), float4 input loads, float2 gts stores ----
    float lsum_hm = 0.0f, lsum_sm = 0.0f;
    int base = b * H * W;
    bool xok = (x4 + 3) < W;

    float mrow[2][4] = {{m00, m01, m02, m03}, {m10, m11, m12, m13}};
#pragma unroll
    for (int r = 0; r < 2; r++) {
        int yy = y + r * BDY;
        if (xok && yy < H) {
            int idx = base + yy * W + x4;
            float4 h4 = *(const float4*)(hm + idx);
            float4 k4 = *(const float4*)(mask + idx);
            float4 s4 = *(const float4*)(sm + idx);
            float4 g4;
            g4.x = ex2_approx(-mrow[r][0]);
            g4.y = ex2_approx(-mrow[r][1]);
            g4.z = ex2_approx(-mrow[r][2]);
            g4.w = ex2_approx(-mrow[r][3]);
            // gts is d_out+2 floats: 8B-aligned only -> two float2 stores
            *(float2*)(gts + idx)     = make_float2(g4.x, g4.y);
            *(float2*)(gts + idx + 2) = make_float2(g4.z, g4.w);
            float d;
            d = h4.x - g4.x; lsum_hm = fmaf(d * d, k4.x, lsum_hm);
            d = h4.y - g4.y; lsum_hm = fmaf(d * d, k4.y, lsum_hm);
            d = h4.z - g4.z; lsum_hm = fmaf(d * d, k4.z, lsum_hm);
            d = h4.w - g4.w; lsum_hm = fmaf(d * d, k4.w, lsum_hm);
            lsum_sm = fmaf(s4.x, s4.x, lsum_sm);
            lsum_sm = fmaf(s4.y, s4.y, lsum_sm);
            lsum_sm = fmaf(s4.z, s4.z, lsum_sm);
            lsum_sm = fmaf(s4.w, s4.w, lsum_sm);
        }
    }

    // ---- deterministic reduction: shuffle within warps, then warp 0 ----
    __shared__ float wh[NTHR / 32];
    __shared__ float ws[NTHR / 32];
    int lane = tid & 31;
    int wid  = tid >> 5;
#pragma unroll
    for (int off = 16; off > 0; off >>= 1) {
        lsum_hm += __shfl_down_sync(0xFFFFFFFFu, lsum_hm, off);
        lsum_sm += __shfl_down_sync(0xFFFFFFFFu, lsum_sm, off);
    }
    if (lane == 0) { wh[wid] = lsum_hm; ws[wid] = lsum_sm; }
    __syncthreads();

    __shared__ int isLast;
    if (tid == 0) {
        float th = 0.0f, ts = 0.0f;
#pragma unroll
        for (int i = 0; i < NTHR / 32; i++) { th += wh[i]; ts += ws[i]; }
        int blin = (b * gridDim.y + blockIdx.y) * gridDim.x + blockIdx.x;
        g_partial[2 * blin + 0] = th;
        g_partial[2 * blin + 1] = ts;
        __threadfence();
        unsigned int v = atomicAdd(&g_count, 1u);
        isLast = (v == (unsigned int)(nblocks - 1));
    }
    __syncthreads();

    // ---- phase C: last block does fixed-order final reduction ----
    if (isLast) {
        volatile float* vp = g_partial;
        float sh = 0.0f, ss = 0.0f;
        for (int i = tid; i < nblocks; i += NTHR) {
            sh += vp[2 * i + 0];
            ss += vp[2 * i + 1];
        }
        __shared__ float rh[NTHR];
        __shared__ float rs[NTHR];
        rh[tid] = sh; rs[tid] = ss;
        __syncthreads();
        for (int sft = NTHR / 2; sft > 0; sft >>= 1) {
            if (tid < sft) { rh[tid] += rh[tid + sft]; rs[tid] += rs[tid + sft]; }
            __syncthreads();
        }
        if (tid == 0) {
            out[0] = rs[0] * invCount;   // scale_loss = mean(sm^2)
            out[1] = rh[0] * invCount;   // hm_loss    = mean((hm-gt)^2 * mask)
            g_count = 0;                 // reset for next graph replay
        }
    }
}

extern "C" void kernel_launch(void* const* d_in, const int* in_sizes, int n_in,
                              void* d_out, int out_size) {
    const float* hm      = (const float*)d_in[0];
    const float* sm      = (const float*)d_in[1];
    const float* gr      = (const float*)d_in[2];
    const float* mask    = (const float*)d_in[3];
    const int*   centers = (const int*)  d_in[4];

    int B  = in_sizes[2];                 // ground_resolution: [B]
    int HW = in_sizes[0] / B;             // pred_hm: [B,1,H,W]
    int H  = 1;
    while ((long long)H * H < (long long)HW) H++;   // 512
    int W  = HW / H;
    int N  = in_sizes[4] / (2 * B);       // centers: [B,N,2]

    float* out = (float*)d_out;
    float* gts = out + (out_size - (size_t)B * HW); // tuple: [sl, hl, gts...]

    dim3 grid((W + TX - 1) / TX, (H + TY - 1) / TY, B);
    dim3 block(BDX, BDY);
    int nblocks = grid.x * grid.y * grid.z;
    fused_kernel<<<grid, block>>>(hm, sm, mask, gr, centers, gts, out,
                                  H, W, N, nblocks,
                                  1.0f / ((float)B * (float)HW));
}